// round 1
// baseline (speedup 1.0000x reference)
#include <cuda_runtime.h>
#include <math.h>

// Problem constants
#define BB   8
#define SS   128
#define HID  256
#define NH   4
#define DH   64
#define FF   1024
#define MM   (BB*SS)      // 1024 rows

// ---------------- scratch (device globals; no allocation allowed) ----------
__device__ float g_q  [MM*HID];
__device__ float g_k  [MM*HID];
__device__ float g_v  [MM*HID];
__device__ float g_aq [MM*HID];
__device__ float g_ak [MM*HID];
__device__ float g_ctx[MM*HID];
__device__ float g_h  [MM*HID];
__device__ float g_t  [MM*HID];
__device__ float g_ff [MM*FF];

// ---------------- generic tiled GEMM: C = A[M,K] @ B[K,N] + bias (+res)(gelu)
// BM=BN=64, BK=16, 256 threads, 4x4 per thread.
__global__ __launch_bounds__(256)
void gemm_kernel(const float* __restrict__ A, const float* __restrict__ Bm,
                 const float* __restrict__ bias, const float* __restrict__ res,
                 float* __restrict__ C, int M, int N, int K, int do_gelu)
{
    const int BM = 64, BN = 64, BK = 16;
    __shared__ float As[BK][BM];
    __shared__ float Bs[BK][BN];

    int tid = threadIdx.x;
    int tx = tid % 16;          // column group
    int ty = tid / 16;          // row group
    int row0 = blockIdx.y * BM;
    int col0 = blockIdx.x * BN;

    float acc[4][4];
#pragma unroll
    for (int i = 0; i < 4; i++)
#pragma unroll
        for (int j = 0; j < 4; j++) acc[i][j] = 0.f;

    for (int k0 = 0; k0 < K; k0 += BK) {
        // load A tile (BM x BK) -> As[c][r]
#pragma unroll
        for (int l = tid; l < BM * BK; l += 256) {
            int r = l / BK, c = l % BK;
            As[c][r] = A[(size_t)(row0 + r) * K + k0 + c];
        }
        // load B tile (BK x BN)
#pragma unroll
        for (int l = tid; l < BK * BN; l += 256) {
            int r = l / BN, c = l % BN;
            Bs[r][c] = Bm[(size_t)(k0 + r) * N + col0 + c];
        }
        __syncthreads();
#pragma unroll
        for (int kk = 0; kk < BK; kk++) {
            float a[4], b[4];
#pragma unroll
            for (int i = 0; i < 4; i++) a[i] = As[kk][ty * 4 + i];
#pragma unroll
            for (int j = 0; j < 4; j++) b[j] = Bs[kk][tx * 4 + j];
#pragma unroll
            for (int i = 0; i < 4; i++)
#pragma unroll
                for (int j = 0; j < 4; j++) acc[i][j] = fmaf(a[i], b[j], acc[i][j]);
        }
        __syncthreads();
    }

#pragma unroll
    for (int i = 0; i < 4; i++) {
        int r = row0 + ty * 4 + i;
#pragma unroll
        for (int j = 0; j < 4; j++) {
            int c = col0 + tx * 4 + j;
            float v = acc[i][j] + bias[c];
            if (res) v += res[(size_t)r * N + c];
            if (do_gelu) v = 0.5f * v * (1.0f + erff(v * 0.70710678118654752f));
            C[(size_t)r * N + c] = v;
        }
    }
}

// ---------------- fused attention ------------------------------------------
// grid = (S, H, B); 128 threads (one per key j). Computes the 5 softmaxes and
// writes ctx row [b, i, h*DH .. h*DH+DH) in [B,S,HID] layout.
__device__ __forceinline__ float softmax128(float x, float* buf)
{
    int t = threadIdx.x;
    buf[t] = x;
    __syncthreads();
#pragma unroll
    for (int s = 64; s > 0; s >>= 1) {
        if (t < s) buf[t] = fmaxf(buf[t], buf[t + s]);
        __syncthreads();
    }
    float m = buf[0];
    __syncthreads();
    float e = expf(x - m);
    buf[t] = e;
    __syncthreads();
#pragma unroll
    for (int s = 64; s > 0; s >>= 1) {
        if (t < s) buf[t] += buf[t + s];
        __syncthreads();
    }
    float r = e / buf[0];
    __syncthreads();
    return r;
}

__global__ __launch_bounds__(128)
void attn_kernel(const float* __restrict__ q, const float* __restrict__ k,
                 const float* __restrict__ v, const float* __restrict__ aq,
                 const float* __restrict__ ak, const float* __restrict__ mask,
                 const float* __restrict__ order_w, const float* __restrict__ order_b,
                 const float* __restrict__ dist_w, const float* __restrict__ dist_b,
                 const float* __restrict__ scalar, float* __restrict__ ctx)
{
    int i = blockIdx.x;     // query index
    int h = blockIdx.y;
    int b = blockIdx.z;
    int j = threadIdx.x;    // key index

    __shared__ float qrow[DH];
    __shared__ float aqrow[DH];
    __shared__ float buf[128];
    __shared__ float prob[128];

    // load q/aq rows for this (b,i,h)
    if (j < DH) {
        size_t base = ((size_t)(b * SS + i) * HID) + h * DH;
        qrow[j]  = q[base + j];
        aqrow[j] = aq[base + j];
    }
    __syncthreads();

    size_t kbase = ((size_t)(b * SS + j) * HID) + h * DH;

    float s = 0.f, as_ = 0.f, ko = 0.f, kd = 0.f, qo = 0.f, qd = 0.f;
#pragma unroll 8
    for (int d = 0; d < DH; d++) {
        float kv = k[kbase + d];
        float akv = ak[kbase + d];
        float qv = qrow[d];
        s   = fmaf(qv, kv, s);
        as_ = fmaf(aqrow[d], akv, as_);
        ko  = fmaf(kv, order_w[DH + d], ko);
        kd  = fmaf(kv, dist_w[DH + d], kd);
        qo  = fmaf(qv, order_w[d], qo);
        qd  = fmaf(qv, dist_w[d], qd);
    }

    // order error
    float pr_o = 1.0f / (1.0f + expf(-(qo + ko + order_b[0])));
    float gd_o = (j > i) ? 1.0f : 0.0f;
    float err_o = logf(pr_o + 1e-24f) * gd_o + logf(1.0f - pr_o + 1e-24f) * (1.0f - gd_o);

    // distance error
    float gd_d = logf(fabsf((float)(j - i)) + 1.0f);
    float pr_d = qd + kd + dist_b[0];
    float sc = scalar[0];
    float diff = gd_d - pr_d;
    float err_d = -0.5f * diff * diff * sc * sc;

    const float inv = 0.125f;  // 1/sqrt(64)
    float mk = mask[((size_t)b * SS + i) * SS + j];

    float rich = s + err_o + err_d;
    float rich_p   = softmax128(rich * inv + mk, buf);
    float origin_p = softmax128(s    * inv + mk, buf);
    float comb_p   = softmax128(origin_p + 0.5f * rich_p, buf);
    float attack_p = softmax128(as_  * inv + mk, buf);
    float final_p  = softmax128(comb_p + 0.5f * attack_p, buf);

    prob[j] = final_p;
    __syncthreads();

    // ctx[b,i,h,:] = sum_j prob[j] * v[b,j,h,:]
    if (j < DH) {
        int d = j;
        float acc = 0.f;
#pragma unroll 4
        for (int jj = 0; jj < SS; jj++) {
            acc = fmaf(prob[jj], v[((size_t)(b * SS + jj) * HID) + h * DH + d], acc);
        }
        ctx[((size_t)(b * SS + i) * HID) + h * DH + d] = acc;
    }
}

// ---------------- LayerNorm over last dim (HID=256), block per row ---------
__global__ __launch_bounds__(256)
void ln_kernel(const float* __restrict__ in, const float* __restrict__ g,
               const float* __restrict__ beta, float* __restrict__ out)
{
    int row = blockIdx.x;
    int t = threadIdx.x;
    __shared__ float buf[256];

    float x = in[(size_t)row * HID + t];
    buf[t] = x;
    __syncthreads();
#pragma unroll
    for (int s = 128; s > 0; s >>= 1) {
        if (t < s) buf[t] += buf[t + s];
        __syncthreads();
    }
    float mean = buf[0] * (1.0f / HID);
    __syncthreads();
    float d = x - mean;
    buf[t] = d * d;
    __syncthreads();
#pragma unroll
    for (int s = 128; s > 0; s >>= 1) {
        if (t < s) buf[t] += buf[t + s];
        __syncthreads();
    }
    float var = buf[0] * (1.0f / HID);
    float inv = rsqrtf(var + 1e-12f);
    out[(size_t)row * HID + t] = d * inv * g[t] + beta[t];
}

// ---------------- launch ----------------------------------------------------
extern "C" void kernel_launch(void* const* d_in, const int* in_sizes, int n_in,
                              void* d_out, int out_size)
{
    const float* x       = (const float*)d_in[0];
    const float* mask    = (const float*)d_in[1];
    const float* Wq      = (const float*)d_in[2];
    const float* bq      = (const float*)d_in[3];
    const float* Wk      = (const float*)d_in[4];
    const float* bk      = (const float*)d_in[5];
    const float* Wv      = (const float*)d_in[6];
    const float* bv      = (const float*)d_in[7];
    const float* order_w = (const float*)d_in[8];
    const float* order_b = (const float*)d_in[9];
    const float* dist_w  = (const float*)d_in[10];
    const float* dist_b  = (const float*)d_in[11];
    const float* scalar  = (const float*)d_in[12];
    const float* AWq     = (const float*)d_in[13];
    const float* Abq     = (const float*)d_in[14];
    const float* AWk     = (const float*)d_in[15];
    const float* Abk     = (const float*)d_in[16];
    const float* Wd      = (const float*)d_in[17];
    const float* bd      = (const float*)d_in[18];
    const float* g1      = (const float*)d_in[19];
    const float* beta1   = (const float*)d_in[20];
    const float* W1      = (const float*)d_in[21];
    const float* b1      = (const float*)d_in[22];
    const float* W2      = (const float*)d_in[23];
    const float* b2      = (const float*)d_in[24];
    const float* g2      = (const float*)d_in[25];
    const float* beta2   = (const float*)d_in[26];
    float* out = (float*)d_out;

    float *q, *k, *v, *aq, *ak, *ctx, *hbuf, *tbuf, *ffb;
    cudaGetSymbolAddress((void**)&q,   g_q);
    cudaGetSymbolAddress((void**)&k,   g_k);
    cudaGetSymbolAddress((void**)&v,   g_v);
    cudaGetSymbolAddress((void**)&aq,  g_aq);
    cudaGetSymbolAddress((void**)&ak,  g_ak);
    cudaGetSymbolAddress((void**)&ctx, g_ctx);
    cudaGetSymbolAddress((void**)&hbuf,g_h);
    cudaGetSymbolAddress((void**)&tbuf,g_t);
    cudaGetSymbolAddress((void**)&ffb, g_ff);

    dim3 blk(256);
    dim3 grd_h(HID / 64, MM / 64);   // N=256
    dim3 grd_f(FF / 64,  MM / 64);   // N=1024

    // QKV projections
    gemm_kernel<<<grd_h, blk>>>(x, Wq, bq, nullptr, q, MM, HID, HID, 0);
    gemm_kernel<<<grd_h, blk>>>(x, Wk, bk, nullptr, k, MM, HID, HID, 0);
    gemm_kernel<<<grd_h, blk>>>(x, Wv, bv, nullptr, v, MM, HID, HID, 0);
    // attack projections (on q,k)
    gemm_kernel<<<grd_h, blk>>>(q, AWq, Abq, nullptr, aq, MM, HID, HID, 0);
    gemm_kernel<<<grd_h, blk>>>(k, AWk, Abk, nullptr, ak, MM, HID, HID, 0);

    // fused attention
    dim3 agrid(SS, NH, BB);
    attn_kernel<<<agrid, 128>>>(q, k, v, aq, ak, mask, order_w, order_b,
                                dist_w, dist_b, scalar, ctx);

    // output projection + residual, LN1
    gemm_kernel<<<grd_h, blk>>>(ctx, Wd, bd, x, tbuf, MM, HID, HID, 0);
    ln_kernel<<<MM, 256>>>(tbuf, g1, beta1, hbuf);

    // FFN
    gemm_kernel<<<grd_f, blk>>>(hbuf, W1, b1, nullptr, ffb, MM, FF, HID, 1);
    gemm_kernel<<<grd_h, blk>>>(ffb, W2, b2, hbuf, tbuf, MM, HID, FF, 0);
    ln_kernel<<<MM, 256>>>(tbuf, g2, beta2, out);
}

// round 2
// speedup vs baseline: 3.5705x; 3.5705x over previous
#include <cuda_runtime.h>
#include <math.h>

#define BB   8
#define SS   128
#define HID  256
#define NH   4
#define DH   64
#define FF   1024
#define MM   (BB*SS)        // 1024 rows
#define PSTR 1280           // proj buffer row stride: q|k|v|aq|ak

// ---------------- scratch ----------------------------------------------------
__device__ float g_proj[MM * PSTR];   // q(0) k(256) v(512) aq(768) ak(1024)
__device__ float g_ctx [MM * HID];
__device__ float g_h   [MM * HID];
__device__ float g_t   [MM * HID];
__device__ float g_ff  [MM * FF];

// =============================================================================
// GEMM tile body: BM = TM*16, BN = 64, BK = 32, 256 threads, TMx4 per thread.
// A [M,K] row-major with stride lda; B [K,NB] row-major stride ldb.
// =============================================================================
template<int TM>
__device__ __forceinline__ void gemm_body(const float* __restrict__ A, int lda,
                                          const float* __restrict__ B, int ldb,
                                          int row0, int bcol0, int K,
                                          float acc[TM][4])
{
    constexpr int BM = TM * 16;
    __shared__ float As[BM][36];      // row-major, pad 36 (16B aligned, conflict-free)
    __shared__ float Bs[32][64];

    const int tid = threadIdx.x;
    const int tx = tid & 15;
    const int ty = tid >> 4;

#pragma unroll
    for (int i = 0; i < TM; i++)
#pragma unroll
        for (int j = 0; j < 4; j++) acc[i][j] = 0.f;

    for (int k0 = 0; k0 < K; k0 += 32) {
        // A tile: BM x 32  (BM*8 float4)
#pragma unroll
        for (int f = tid; f < BM * 8; f += 256) {
            int r = f >> 3, c4 = (f & 7) << 2;
            float4 t = *(const float4*)&A[(size_t)(row0 + r) * lda + k0 + c4];
            *(float4*)&As[r][c4] = t;
        }
        // B tile: 32 x 64 (512 float4)
#pragma unroll
        for (int f = tid; f < 512; f += 256) {
            int r = f >> 4, c4 = (f & 15) << 2;
            *(float4*)&Bs[r][c4] = *(const float4*)&B[(size_t)(k0 + r) * ldb + bcol0 + c4];
        }
        __syncthreads();
#pragma unroll
        for (int kk = 0; kk < 32; kk++) {
            float4 b4 = *(const float4*)&Bs[kk][tx << 2];
            float a[TM];
#pragma unroll
            for (int i = 0; i < TM; i++) a[i] = As[ty * TM + i][kk];
#pragma unroll
            for (int i = 0; i < TM; i++) {
                acc[i][0] = fmaf(a[i], b4.x, acc[i][0]);
                acc[i][1] = fmaf(a[i], b4.y, acc[i][1]);
                acc[i][2] = fmaf(a[i], b4.z, acc[i][2]);
                acc[i][3] = fmaf(a[i], b4.w, acc[i][3]);
            }
        }
        __syncthreads();
    }
}

// Generic GEMM: C[M,N] = A[M,K]@B[K,N] + bias (+res)(gelu)
template<int TM>
__global__ __launch_bounds__(256)
void gemm_g(const float* __restrict__ A, const float* __restrict__ B,
            const float* __restrict__ bias, const float* __restrict__ res,
            float* __restrict__ C, int N, int K, int do_gelu)
{
    constexpr int BM = TM * 16;
    const int row0 = blockIdx.y * BM;
    const int col0 = blockIdx.x * 64;
    float acc[TM][4];
    gemm_body<TM>(A, K, B, N, row0, col0, K, acc);

    const int tx = threadIdx.x & 15, ty = threadIdx.x >> 4;
#pragma unroll
    for (int i = 0; i < TM; i++) {
        int r = row0 + ty * TM + i;
#pragma unroll
        for (int j = 0; j < 4; j++) {
            int c = col0 + (tx << 2) + j;
            float v = acc[i][j] + bias[c];
            if (res) v += res[(size_t)r * N + c];
            if (do_gelu) v = 0.5f * v * (1.0f + erff(v * 0.70710678118654752f));
            C[(size_t)r * N + c] = v;
        }
    }
}

// proj1: q|k|v = x @ {Wq,Wk,Wv} + bias  -> g_proj cols [0,768)
__global__ __launch_bounds__(256)
void proj1_kernel(const float* __restrict__ x,
                  const float* __restrict__ Wq, const float* __restrict__ bq,
                  const float* __restrict__ Wk, const float* __restrict__ bk,
                  const float* __restrict__ Wv, const float* __restrict__ bv,
                  float* __restrict__ P)
{
    const int seg = blockIdx.x >> 2;                 // 0 q, 1 k, 2 v
    const float* W = seg == 0 ? Wq : (seg == 1 ? Wk : Wv);
    const float* bias = seg == 0 ? bq : (seg == 1 ? bk : bv);
    const int wcol0 = (blockIdx.x & 3) * 64;
    const int row0 = blockIdx.y * 64;

    float acc[4][4];
    gemm_body<4>(x, HID, W, HID, row0, wcol0, HID, acc);

    const int tx = threadIdx.x & 15, ty = threadIdx.x >> 4;
    const int ocol0 = blockIdx.x * 64;
#pragma unroll
    for (int i = 0; i < 4; i++) {
        int r = row0 + ty * 4 + i;
#pragma unroll
        for (int j = 0; j < 4; j++) {
            int c = (tx << 2) + j;
            P[(size_t)r * PSTR + ocol0 + c] = acc[i][j] + bias[wcol0 + c];
        }
    }
}

// proj2: aq = q@AWq + Abq, ak = k@AWk + Abk -> g_proj cols [768,1280)
__global__ __launch_bounds__(256)
void proj2_kernel(const float* __restrict__ P_in,
                  const float* __restrict__ AWq, const float* __restrict__ Abq,
                  const float* __restrict__ AWk, const float* __restrict__ Abk,
                  float* __restrict__ P)
{
    const int seg = blockIdx.x >> 2;                 // 0 aq(from q), 1 ak(from k)
    const float* A = P_in + seg * 256;               // q at 0, k at 256
    const float* W = seg ? AWk : AWq;
    const float* bias = seg ? Abk : Abq;
    const int wcol0 = (blockIdx.x & 3) * 64;
    const int row0 = blockIdx.y * 64;

    float acc[4][4];
    gemm_body<4>(A, PSTR, W, HID, row0, wcol0, HID, acc);

    const int tx = threadIdx.x & 15, ty = threadIdx.x >> 4;
    const int ocol0 = 768 + blockIdx.x * 64;
#pragma unroll
    for (int i = 0; i < 4; i++) {
        int r = row0 + ty * 4 + i;
#pragma unroll
        for (int j = 0; j < 4; j++) {
            int c = (tx << 2) + j;
            P[(size_t)r * PSTR + ocol0 + c] = acc[i][j] + bias[wcol0 + c];
        }
    }
}

// =============================================================================
// Fused attention: block = 8 warps = 8 queries of one (b,h); grid (16, H, B).
// Shared tile (128x68) reused in phases: k -> ak -> v. All softmaxes are
// shuffle-only warp reductions.
// =============================================================================
__device__ __forceinline__ void softmax4(const float x[4], float p[4])
{
    float m = fmaxf(fmaxf(x[0], x[1]), fmaxf(x[2], x[3]));
#pragma unroll
    for (int o = 16; o; o >>= 1) m = fmaxf(m, __shfl_xor_sync(0xffffffffu, m, o));
    float e0 = __expf(x[0] - m), e1 = __expf(x[1] - m);
    float e2 = __expf(x[2] - m), e3 = __expf(x[3] - m);
    float s = e0 + e1 + e2 + e3;
#pragma unroll
    for (int o = 16; o; o >>= 1) s += __shfl_xor_sync(0xffffffffu, s, o);
    float r = 1.f / s;
    p[0] = e0 * r; p[1] = e1 * r; p[2] = e2 * r; p[3] = e3 * r;
}

__global__ __launch_bounds__(256)
void attn_kernel(const float* __restrict__ P, const float* __restrict__ mask,
                 const float* __restrict__ order_w, const float* __restrict__ order_b,
                 const float* __restrict__ dist_w, const float* __restrict__ dist_b,
                 const float* __restrict__ scalar, float* __restrict__ ctx)
{
    __shared__ float tile[128][68];     // k, then ak, then v
    __shared__ float qsh[8][64];        // q, then aq
    __shared__ float probs[8][128];
    __shared__ float kokd[128][2];
    __shared__ float wsh[256];          // order_w[128] | dist_w[128]

    const int tid = threadIdx.x;
    const int lane = tid & 31;
    const int w = tid >> 5;
    const int h = blockIdx.y, b = blockIdx.z;
    const int i0 = blockIdx.x * 8;
    const int i = i0 + w;

    const size_t rowbase = ((size_t)b * SS) * PSTR + h * DH;

    // ---- phase 1: k tile + q rows + weights
#pragma unroll
    for (int f = tid; f < 128 * 16; f += 256) {
        int j = f >> 4, d4 = (f & 15) << 2;
        *(float4*)&tile[j][d4] = *(const float4*)&P[rowbase + (size_t)j * PSTR + 256 + d4];
    }
#pragma unroll
    for (int f = tid; f < 8 * 16; f += 256) {
        int r = f >> 4, d4 = (f & 15) << 2;
        *(float4*)&qsh[r][d4] = *(const float4*)&P[rowbase + (size_t)(i0 + r) * PSTR + d4];
    }
    wsh[tid] = (tid < 128) ? order_w[tid] : dist_w[tid - 128];
    __syncthreads();

    // q dot k
    float s[4] = {0, 0, 0, 0};
#pragma unroll
    for (int d4 = 0; d4 < 64; d4 += 4) {
        float4 qv = *(const float4*)&qsh[w][d4];
#pragma unroll
        for (int jj = 0; jj < 4; jj++) {
            float4 kv = *(const float4*)&tile[lane + 32 * jj][d4];
            s[jj] = fmaf(qv.x, kv.x, fmaf(qv.y, kv.y, fmaf(qv.z, kv.z, fmaf(qv.w, kv.w, s[jj]))));
        }
    }
    // per-key order/dist projections (once per block)
    if (tid < 128) {
        float ko = 0, kd = 0;
#pragma unroll
        for (int d4 = 0; d4 < 64; d4 += 4) {
            float4 kv = *(const float4*)&tile[tid][d4];
            float4 ov = *(const float4*)&wsh[64 + d4];
            float4 dv = *(const float4*)&wsh[192 + d4];
            ko = fmaf(kv.x, ov.x, fmaf(kv.y, ov.y, fmaf(kv.z, ov.z, fmaf(kv.w, ov.w, ko))));
            kd = fmaf(kv.x, dv.x, fmaf(kv.y, dv.y, fmaf(kv.z, dv.z, fmaf(kv.w, dv.w, kd))));
        }
        kokd[tid][0] = ko; kokd[tid][1] = kd;
    }
    // per-query order/dist projections (q still in qsh)
    float qo = qsh[w][lane] * wsh[lane] + qsh[w][lane + 32] * wsh[32 + lane];
    float qd = qsh[w][lane] * wsh[128 + lane] + qsh[w][lane + 32] * wsh[160 + lane];
#pragma unroll
    for (int o = 16; o; o >>= 1) {
        qo += __shfl_xor_sync(0xffffffffu, qo, o);
        qd += __shfl_xor_sync(0xffffffffu, qd, o);
    }
    __syncthreads();

    // ---- phase 2: ak tile + aq rows
#pragma unroll
    for (int f = tid; f < 128 * 16; f += 256) {
        int j = f >> 4, d4 = (f & 15) << 2;
        *(float4*)&tile[j][d4] = *(const float4*)&P[rowbase + (size_t)j * PSTR + 1024 + d4];
    }
#pragma unroll
    for (int f = tid; f < 8 * 16; f += 256) {
        int r = f >> 4, d4 = (f & 15) << 2;
        *(float4*)&qsh[r][d4] = *(const float4*)&P[rowbase + (size_t)(i0 + r) * PSTR + 768 + d4];
    }
    __syncthreads();

    float as[4] = {0, 0, 0, 0};
#pragma unroll
    for (int d4 = 0; d4 < 64; d4 += 4) {
        float4 qv = *(const float4*)&qsh[w][d4];
#pragma unroll
        for (int jj = 0; jj < 4; jj++) {
            float4 kv = *(const float4*)&tile[lane + 32 * jj][d4];
            as[jj] = fmaf(qv.x, kv.x, fmaf(qv.y, kv.y, fmaf(qv.z, kv.z, fmaf(qv.w, kv.w, as[jj]))));
        }
    }
    __syncthreads();   // ak reads done; tile free for v

    // issue v loads (overlap with softmax math below)
    float4 vreg[8];
#pragma unroll
    for (int t = 0; t < 8; t++) {
        int f = tid + t * 256;
        int j = f >> 4, d4 = (f & 15) << 2;
        vreg[t] = *(const float4*)&P[rowbase + (size_t)j * PSTR + 512 + d4];
    }

    // ---- error terms + 5 chained softmaxes (registers + shuffles only)
    const float ob = order_b[0], db = dist_b[0], sc = scalar[0];
    const float inv = 0.125f;
    float rich[4], orig[4], att[4];
#pragma unroll
    for (int jj = 0; jj < 4; jj++) {
        int j = lane + 32 * jj;
        float pr_o = 1.f / (1.f + __expf(-(qo + kokd[j][0] + ob)));
        float gd = (j > i) ? 1.f : 0.f;
        float err_o = __logf(pr_o + 1e-24f) * gd + __logf(1.f - pr_o + 1e-24f) * (1.f - gd);
        float gdd = __logf(fabsf((float)(j - i)) + 1.f);
        float diff = gdd - (qd + kokd[j][1] + db);
        float err_d = -0.5f * diff * diff * sc * sc;
        float mk = mask[((size_t)b * SS + i) * SS + j];
        rich[jj] = (s[jj] + err_o + err_d) * inv + mk;
        orig[jj] = s[jj] * inv + mk;
        att[jj]  = as[jj] * inv + mk;
    }
    float rich_p[4], orig_p[4], att_p[4], comb[4], comb_p[4], fin[4], fin_p[4];
    softmax4(rich, rich_p);
    softmax4(orig, orig_p);
    softmax4(att, att_p);
#pragma unroll
    for (int jj = 0; jj < 4; jj++) comb[jj] = orig_p[jj] + 0.5f * rich_p[jj];
    softmax4(comb, comb_p);
#pragma unroll
    for (int jj = 0; jj < 4; jj++) fin[jj] = comb_p[jj] + 0.5f * att_p[jj];
    softmax4(fin, fin_p);
#pragma unroll
    for (int jj = 0; jj < 4; jj++) probs[w][lane + 32 * jj] = fin_p[jj];

    // commit v tile
#pragma unroll
    for (int t = 0; t < 8; t++) {
        int f = tid + t * 256;
        int j = f >> 4, d4 = (f & 15) << 2;
        *(float4*)&tile[j][d4] = vreg[t];
    }
    __syncthreads();

    // context: ctx[b,i,h,d] = sum_j p_j * v[j,d]
    float c0 = 0.f, c1 = 0.f;
#pragma unroll 4
    for (int j = 0; j < 128; j++) {
        float p = probs[w][j];
        c0 = fmaf(p, tile[j][lane], c0);
        c1 = fmaf(p, tile[j][lane + 32], c1);
    }
    size_t obase = ((size_t)(b * SS + i)) * HID + h * DH;
    ctx[obase + lane] = c0;
    ctx[obase + lane + 32] = c1;
}

// ---------------- LayerNorm (HID=256), block per row ------------------------
__global__ __launch_bounds__(256)
void ln_kernel(const float* __restrict__ in, const float* __restrict__ g,
               const float* __restrict__ beta, float* __restrict__ out)
{
    int row = blockIdx.x;
    int t = threadIdx.x;
    int lane = t & 31, w = t >> 5;
    __shared__ float red[8];

    float x = in[(size_t)row * HID + t];
    float v = x;
#pragma unroll
    for (int o = 16; o; o >>= 1) v += __shfl_xor_sync(0xffffffffu, v, o);
    if (lane == 0) red[w] = v;
    __syncthreads();
    float mean;
    {
        float r = (lane < 8) ? red[lane] : 0.f;
#pragma unroll
        for (int o = 4; o; o >>= 1) r += __shfl_xor_sync(0xffffffffu, r, o);
        mean = __shfl_sync(0xffffffffu, r, 0) * (1.0f / HID);
    }
    float d = x - mean;
    v = d * d;
#pragma unroll
    for (int o = 16; o; o >>= 1) v += __shfl_xor_sync(0xffffffffu, v, o);
    __syncthreads();
    if (lane == 0) red[w] = v;
    __syncthreads();
    float var;
    {
        float r = (lane < 8) ? red[lane] : 0.f;
#pragma unroll
        for (int o = 4; o; o >>= 1) r += __shfl_xor_sync(0xffffffffu, r, o);
        var = __shfl_sync(0xffffffffu, r, 0) * (1.0f / HID);
    }
    float invs = rsqrtf(var + 1e-12f);
    out[(size_t)row * HID + t] = d * invs * g[t] + beta[t];
}

// ---------------- launch -----------------------------------------------------
extern "C" void kernel_launch(void* const* d_in, const int* in_sizes, int n_in,
                              void* d_out, int out_size)
{
    const float* x       = (const float*)d_in[0];
    const float* mask    = (const float*)d_in[1];
    const float* Wq      = (const float*)d_in[2];
    const float* bq      = (const float*)d_in[3];
    const float* Wk      = (const float*)d_in[4];
    const float* bk      = (const float*)d_in[5];
    const float* Wv      = (const float*)d_in[6];
    const float* bv      = (const float*)d_in[7];
    const float* order_w = (const float*)d_in[8];
    const float* order_b = (const float*)d_in[9];
    const float* dist_w  = (const float*)d_in[10];
    const float* dist_b  = (const float*)d_in[11];
    const float* scalar  = (const float*)d_in[12];
    const float* AWq     = (const float*)d_in[13];
    const float* Abq     = (const float*)d_in[14];
    const float* AWk     = (const float*)d_in[15];
    const float* Abk     = (const float*)d_in[16];
    const float* Wd      = (const float*)d_in[17];
    const float* bd      = (const float*)d_in[18];
    const float* g1      = (const float*)d_in[19];
    const float* beta1   = (const float*)d_in[20];
    const float* W1      = (const float*)d_in[21];
    const float* b1      = (const float*)d_in[22];
    const float* W2      = (const float*)d_in[23];
    const float* b2      = (const float*)d_in[24];
    const float* g2      = (const float*)d_in[25];
    const float* beta2   = (const float*)d_in[26];
    float* out = (float*)d_out;

    float *P, *ctx, *hbuf, *tbuf, *ffb;
    cudaGetSymbolAddress((void**)&P,    g_proj);
    cudaGetSymbolAddress((void**)&ctx,  g_ctx);
    cudaGetSymbolAddress((void**)&hbuf, g_h);
    cudaGetSymbolAddress((void**)&tbuf, g_t);
    cudaGetSymbolAddress((void**)&ffb,  g_ff);

    // q,k,v then aq,ak (batched projections)
    proj1_kernel<<<dim3(12, 16), 256>>>(x, Wq, bq, Wk, bk, Wv, bv, P);
    proj2_kernel<<<dim3(8, 16), 256>>>(P, AWq, Abq, AWk, Abk, P);

    // fused attention
    attn_kernel<<<dim3(SS / 8, NH, BB), 256>>>(P, mask, order_w, order_b,
                                               dist_w, dist_b, scalar, ctx);

    // output projection + residual, LN1
    gemm_g<2><<<dim3(4, 32), 256>>>(ctx, Wd, bd, x, tbuf, HID, HID, 0);
    ln_kernel<<<MM, 256>>>(tbuf, g1, beta1, hbuf);

    // FFN
    gemm_g<4><<<dim3(16, 16), 256>>>(hbuf, W1, b1, nullptr, ffb, FF, HID, 1);
    gemm_g<2><<<dim3(4, 32), 256>>>(ffb, W2, b2, hbuf, tbuf, HID, FF, 0);
    ln_kernel<<<MM, 256>>>(tbuf, g2, beta2, out);
}

// round 3
// speedup vs baseline: 4.0521x; 1.1349x over previous
#include <cuda_runtime.h>
#include <math.h>

#define BB   8
#define SS   128
#define HID  256
#define NH   4
#define DH   64
#define FF   1024
#define MM   (BB*SS)        // 1024 rows
#define PSTR 1280           // proj buffer row stride: q|k|v|aq|ak

// ---------------- scratch ----------------------------------------------------
__device__ float g_proj[MM * PSTR];   // q(0) k(256) v(512) aq(768) ak(1024)
__device__ float g_ctx [MM * HID];
__device__ float g_h   [MM * HID];
__device__ float g_part[2 * MM * HID]; // split-K partials
__device__ float g_ff  [MM * FF];
__device__ float g_wf  [HID * 512];   // fused attack weights: [256][512] (aq|ak)
__device__ float g_bf  [512];         // fused attack biases

// =============================================================================
// Software-pipelined GEMM tile body. BM = TM*16, BN = 64, BK = 32, 256 threads.
// Prefetches next K-tile's global loads into registers during compute.
// =============================================================================
template<int TM>
__device__ __forceinline__ void gemm_body(const float* __restrict__ A, int lda,
                                          const float* __restrict__ B, int ldb,
                                          int row0, int bcol0, int K,
                                          float acc[TM][4])
{
    constexpr int BM = TM * 16;
    constexpr int AU = BM / 32;         // float4 A-loads per thread
    __shared__ float As[BM][36];
    __shared__ float Bs[32][68];

    const int tid = threadIdx.x;
    const int tx = tid & 15;
    const int ty = tid >> 4;

    int ar[AU], ac[AU];
#pragma unroll
    for (int u = 0; u < AU; u++) { int f = tid + 256 * u; ar[u] = f >> 3; ac[u] = (f & 7) << 2; }
    int br[2], bc[2];
#pragma unroll
    for (int u = 0; u < 2; u++)  { int f = tid + 256 * u; br[u] = f >> 4; bc[u] = (f & 15) << 2; }

    float4 aR[AU], bR[2];
#pragma unroll
    for (int u = 0; u < AU; u++)
        aR[u] = *(const float4*)&A[(size_t)(row0 + ar[u]) * lda + ac[u]];
#pragma unroll
    for (int u = 0; u < 2; u++)
        bR[u] = *(const float4*)&B[(size_t)br[u] * ldb + bcol0 + bc[u]];

#pragma unroll
    for (int i = 0; i < TM; i++)
#pragma unroll
        for (int j = 0; j < 4; j++) acc[i][j] = 0.f;

    for (int k0 = 0; k0 < K; k0 += 32) {
        __syncthreads();
#pragma unroll
        for (int u = 0; u < AU; u++) *(float4*)&As[ar[u]][ac[u]] = aR[u];
#pragma unroll
        for (int u = 0; u < 2; u++)  *(float4*)&Bs[br[u]][bc[u]] = bR[u];
        __syncthreads();

        if (k0 + 32 < K) {
#pragma unroll
            for (int u = 0; u < AU; u++)
                aR[u] = *(const float4*)&A[(size_t)(row0 + ar[u]) * lda + k0 + 32 + ac[u]];
#pragma unroll
            for (int u = 0; u < 2; u++)
                bR[u] = *(const float4*)&B[(size_t)(k0 + 32 + br[u]) * ldb + bcol0 + bc[u]];
        }

#pragma unroll
        for (int kk = 0; kk < 32; kk++) {
            float4 b4 = *(const float4*)&Bs[kk][tx << 2];
            float a[TM];
#pragma unroll
            for (int i = 0; i < TM; i++) a[i] = As[ty * TM + i][kk];
#pragma unroll
            for (int i = 0; i < TM; i++) {
                acc[i][0] = fmaf(a[i], b4.x, acc[i][0]);
                acc[i][1] = fmaf(a[i], b4.y, acc[i][1]);
                acc[i][2] = fmaf(a[i], b4.z, acc[i][2]);
                acc[i][3] = fmaf(a[i], b4.w, acc[i][3]);
            }
        }
    }
}

// =============================================================================
// fusew: Wf[:,0:256] = Wq@AWq, Wf[:,256:512] = Wk@AWk; plus fused biases
// bf[0:256] = bq@AWq + Abq, bf[256:512] = bk@AWk + Abk.
// grid (8,5): y<4 -> GEMM tiles; y==4 -> bias rows.
// =============================================================================
__global__ __launch_bounds__(256)
void fusew_kernel(const float* __restrict__ Wq, const float* __restrict__ bq,
                  const float* __restrict__ Wk, const float* __restrict__ bk,
                  const float* __restrict__ AWq, const float* __restrict__ Abq,
                  const float* __restrict__ AWk, const float* __restrict__ Abk,
                  float* __restrict__ Wf, float* __restrict__ bf)
{
    const int seg = blockIdx.x >> 2;                 // 0: q-path, 1: k-path
    const int wcol0 = (blockIdx.x & 3) * 64;

    if (blockIdx.y == 4) {
        // fused bias: bf[seg*256 + col] = sum_d bin[d]*AW[d][col] + Ab[col]
        const float* bin = seg ? bk : bq;
        const float* AW  = seg ? AWk : AWq;
        const float* Ab  = seg ? Abk : Abq;
        __shared__ float red[256];
        int t = threadIdx.x;
        int c = t & 63, part = t >> 6;
        float s = 0.f;
        for (int d = part * 64; d < part * 64 + 64; d++)
            s += bin[d] * AW[(size_t)d * HID + wcol0 + c];
        red[t] = s;
        __syncthreads();
        if (part == 0)
            bf[seg * 256 + wcol0 + c] = red[c] + red[64 + c] + red[128 + c] + red[192 + c]
                                        + Ab[wcol0 + c];
        return;
    }

    const float* A = seg ? Wk : Wq;
    const float* B = seg ? AWk : AWq;
    const int row0 = blockIdx.y * 64;
    float acc[4][4];
    gemm_body<4>(A, HID, B, HID, row0, wcol0, HID, acc);

    const int tx = threadIdx.x & 15, ty = threadIdx.x >> 4;
#pragma unroll
    for (int i = 0; i < 4; i++) {
        int r = row0 + ty * 4 + i;
#pragma unroll
        for (int j = 0; j < 4; j++)
            Wf[(size_t)r * 512 + seg * 256 + wcol0 + (tx << 2) + j] = acc[i][j];
    }
}

// =============================================================================
// proj: all five projections from x in one kernel. grid (20,16).
// seg 0..2: W{q,k,v}; seg 3: fused aq; seg 4: fused ak.
// =============================================================================
__global__ __launch_bounds__(256)
void proj_kernel(const float* __restrict__ x,
                 const float* __restrict__ Wq, const float* __restrict__ bq,
                 const float* __restrict__ Wk, const float* __restrict__ bk,
                 const float* __restrict__ Wv, const float* __restrict__ bv,
                 const float* __restrict__ Wf, const float* __restrict__ bf,
                 float* __restrict__ P)
{
    const int seg = blockIdx.x >> 2;
    const int wcol0 = (blockIdx.x & 3) * 64;
    const int row0 = blockIdx.y * 64;

    const float* W; const float* bias; int ldb; int bcol;
    if      (seg == 0) { W = Wq; bias = bq;        ldb = HID; bcol = wcol0; }
    else if (seg == 1) { W = Wk; bias = bk;        ldb = HID; bcol = wcol0; }
    else if (seg == 2) { W = Wv; bias = bv;        ldb = HID; bcol = wcol0; }
    else if (seg == 3) { W = Wf; bias = bf;        ldb = 512; bcol = wcol0; }
    else               { W = Wf; bias = bf + 256;  ldb = 512; bcol = 256 + wcol0; }

    float acc[4][4];
    gemm_body<4>(x, HID, W, ldb, row0, bcol, HID, acc);

    const int tx = threadIdx.x & 15, ty = threadIdx.x >> 4;
    const int ocol0 = blockIdx.x * 64;
#pragma unroll
    for (int i = 0; i < 4; i++) {
        int r = row0 + ty * 4 + i;
#pragma unroll
        for (int j = 0; j < 4; j++) {
            int c = (tx << 2) + j;
            P[(size_t)r * PSTR + ocol0 + c] = acc[i][j] + bias[wcol0 + c];
        }
    }
}

// =============================================================================
// Generic GEMM with bias (+gelu): used for W1. grid (N/64, M/BM).
// =============================================================================
template<int TM>
__global__ __launch_bounds__(256)
void gemm_g(const float* __restrict__ A, const float* __restrict__ B,
            const float* __restrict__ bias, float* __restrict__ C,
            int N, int K, int do_gelu)
{
    constexpr int BM = TM * 16;
    const int row0 = blockIdx.y * BM;
    const int col0 = blockIdx.x * 64;
    float acc[TM][4];
    gemm_body<TM>(A, K, B, N, row0, col0, K, acc);

    const int tx = threadIdx.x & 15, ty = threadIdx.x >> 4;
#pragma unroll
    for (int i = 0; i < TM; i++) {
        int r = row0 + ty * TM + i;
#pragma unroll
        for (int j = 0; j < 4; j++) {
            int c = col0 + (tx << 2) + j;
            float v = acc[i][j] + bias[c];
            if (do_gelu) v = 0.5f * v * (1.0f + erff(v * 0.70710678118654752f));
            C[(size_t)r * N + c] = v;
        }
    }
}

// =============================================================================
// Split-K partial GEMM (no bias). blockIdx.z selects K-half.
// Writes Cp[z*M*N + r*N + c]. grid (N/64, M/BM, 2).
// =============================================================================
template<int TM>
__global__ __launch_bounds__(256)
void gemm_partial(const float* __restrict__ A, const float* __restrict__ B,
                  float* __restrict__ Cp, int N, int K)
{
    constexpr int BM = TM * 16;
    const int ks = blockIdx.z;
    const int Kh = K >> 1;
    const int row0 = blockIdx.y * BM;
    const int col0 = blockIdx.x * 64;
    float acc[TM][4];
    gemm_body<TM>(A + (size_t)ks * Kh, K, B + (size_t)ks * Kh * N, N, row0, col0, Kh, acc);

    float* C = Cp + (size_t)ks * MM * HID;
    const int tx = threadIdx.x & 15, ty = threadIdx.x >> 4;
#pragma unroll
    for (int i = 0; i < TM; i++) {
        int r = row0 + ty * TM + i;
#pragma unroll
        for (int j = 0; j < 4; j++) {
            int c = col0 + (tx << 2) + j;
            C[(size_t)r * N + c] = acc[i][j];
        }
    }
}

// =============================================================================
// Fused attention (unchanged from R2): block = 8 warps = 8 queries of one (b,h).
// =============================================================================
__device__ __forceinline__ void softmax4(const float x[4], float p[4])
{
    float m = fmaxf(fmaxf(x[0], x[1]), fmaxf(x[2], x[3]));
#pragma unroll
    for (int o = 16; o; o >>= 1) m = fmaxf(m, __shfl_xor_sync(0xffffffffu, m, o));
    float e0 = __expf(x[0] - m), e1 = __expf(x[1] - m);
    float e2 = __expf(x[2] - m), e3 = __expf(x[3] - m);
    float s = e0 + e1 + e2 + e3;
#pragma unroll
    for (int o = 16; o; o >>= 1) s += __shfl_xor_sync(0xffffffffu, s, o);
    float r = 1.f / s;
    p[0] = e0 * r; p[1] = e1 * r; p[2] = e2 * r; p[3] = e3 * r;
}

__global__ __launch_bounds__(256)
void attn_kernel(const float* __restrict__ P, const float* __restrict__ mask,
                 const float* __restrict__ order_w, const float* __restrict__ order_b,
                 const float* __restrict__ dist_w, const float* __restrict__ dist_b,
                 const float* __restrict__ scalar, float* __restrict__ ctx)
{
    __shared__ float tile[128][68];
    __shared__ float qsh[8][64];
    __shared__ float probs[8][128];
    __shared__ float kokd[128][2];
    __shared__ float wsh[256];

    const int tid = threadIdx.x;
    const int lane = tid & 31;
    const int w = tid >> 5;
    const int h = blockIdx.y, b = blockIdx.z;
    const int i0 = blockIdx.x * 8;
    const int i = i0 + w;

    const size_t rowbase = ((size_t)b * SS) * PSTR + h * DH;

#pragma unroll
    for (int f = tid; f < 128 * 16; f += 256) {
        int j = f >> 4, d4 = (f & 15) << 2;
        *(float4*)&tile[j][d4] = *(const float4*)&P[rowbase + (size_t)j * PSTR + 256 + d4];
    }
#pragma unroll
    for (int f = tid; f < 8 * 16; f += 256) {
        int r = f >> 4, d4 = (f & 15) << 2;
        *(float4*)&qsh[r][d4] = *(const float4*)&P[rowbase + (size_t)(i0 + r) * PSTR + d4];
    }
    wsh[tid] = (tid < 128) ? order_w[tid] : dist_w[tid - 128];
    __syncthreads();

    float s[4] = {0, 0, 0, 0};
#pragma unroll
    for (int d4 = 0; d4 < 64; d4 += 4) {
        float4 qv = *(const float4*)&qsh[w][d4];
#pragma unroll
        for (int jj = 0; jj < 4; jj++) {
            float4 kv = *(const float4*)&tile[lane + 32 * jj][d4];
            s[jj] = fmaf(qv.x, kv.x, fmaf(qv.y, kv.y, fmaf(qv.z, kv.z, fmaf(qv.w, kv.w, s[jj]))));
        }
    }
    if (tid < 128) {
        float ko = 0, kd = 0;
#pragma unroll
        for (int d4 = 0; d4 < 64; d4 += 4) {
            float4 kv = *(const float4*)&tile[tid][d4];
            float4 ov = *(const float4*)&wsh[64 + d4];
            float4 dv = *(const float4*)&wsh[192 + d4];
            ko = fmaf(kv.x, ov.x, fmaf(kv.y, ov.y, fmaf(kv.z, ov.z, fmaf(kv.w, ov.w, ko))));
            kd = fmaf(kv.x, dv.x, fmaf(kv.y, dv.y, fmaf(kv.z, dv.z, fmaf(kv.w, dv.w, kd))));
        }
        kokd[tid][0] = ko; kokd[tid][1] = kd;
    }
    float qo = qsh[w][lane] * wsh[lane] + qsh[w][lane + 32] * wsh[32 + lane];
    float qd = qsh[w][lane] * wsh[128 + lane] + qsh[w][lane + 32] * wsh[160 + lane];
#pragma unroll
    for (int o = 16; o; o >>= 1) {
        qo += __shfl_xor_sync(0xffffffffu, qo, o);
        qd += __shfl_xor_sync(0xffffffffu, qd, o);
    }
    __syncthreads();

#pragma unroll
    for (int f = tid; f < 128 * 16; f += 256) {
        int j = f >> 4, d4 = (f & 15) << 2;
        *(float4*)&tile[j][d4] = *(const float4*)&P[rowbase + (size_t)j * PSTR + 1024 + d4];
    }
#pragma unroll
    for (int f = tid; f < 8 * 16; f += 256) {
        int r = f >> 4, d4 = (f & 15) << 2;
        *(float4*)&qsh[r][d4] = *(const float4*)&P[rowbase + (size_t)(i0 + r) * PSTR + 768 + d4];
    }
    __syncthreads();

    float as[4] = {0, 0, 0, 0};
#pragma unroll
    for (int d4 = 0; d4 < 64; d4 += 4) {
        float4 qv = *(const float4*)&qsh[w][d4];
#pragma unroll
        for (int jj = 0; jj < 4; jj++) {
            float4 kv = *(const float4*)&tile[lane + 32 * jj][d4];
            as[jj] = fmaf(qv.x, kv.x, fmaf(qv.y, kv.y, fmaf(qv.z, kv.z, fmaf(qv.w, kv.w, as[jj]))));
        }
    }
    __syncthreads();

    float4 vreg[8];
#pragma unroll
    for (int t = 0; t < 8; t++) {
        int f = tid + t * 256;
        int j = f >> 4, d4 = (f & 15) << 2;
        vreg[t] = *(const float4*)&P[rowbase + (size_t)j * PSTR + 512 + d4];
    }

    const float ob = order_b[0], db = dist_b[0], sc = scalar[0];
    const float inv = 0.125f;
    float rich[4], orig[4], att[4];
#pragma unroll
    for (int jj = 0; jj < 4; jj++) {
        int j = lane + 32 * jj;
        float pr_o = 1.f / (1.f + __expf(-(qo + kokd[j][0] + ob)));
        float gd = (j > i) ? 1.f : 0.f;
        float err_o = __logf(pr_o + 1e-24f) * gd + __logf(1.f - pr_o + 1e-24f) * (1.f - gd);
        float gdd = __logf(fabsf((float)(j - i)) + 1.f);
        float diff = gdd - (qd + kokd[j][1] + db);
        float err_d = -0.5f * diff * diff * sc * sc;
        float mk = mask[((size_t)b * SS + i) * SS + j];
        rich[jj] = (s[jj] + err_o + err_d) * inv + mk;
        orig[jj] = s[jj] * inv + mk;
        att[jj]  = as[jj] * inv + mk;
    }
    float rich_p[4], orig_p[4], att_p[4], comb[4], comb_p[4], fin[4], fin_p[4];
    softmax4(rich, rich_p);
    softmax4(orig, orig_p);
    softmax4(att, att_p);
#pragma unroll
    for (int jj = 0; jj < 4; jj++) comb[jj] = orig_p[jj] + 0.5f * rich_p[jj];
    softmax4(comb, comb_p);
#pragma unroll
    for (int jj = 0; jj < 4; jj++) fin[jj] = comb_p[jj] + 0.5f * att_p[jj];
    softmax4(fin, fin_p);
#pragma unroll
    for (int jj = 0; jj < 4; jj++) probs[w][lane + 32 * jj] = fin_p[jj];

#pragma unroll
    for (int t = 0; t < 8; t++) {
        int f = tid + t * 256;
        int j = f >> 4, d4 = (f & 15) << 2;
        *(float4*)&tile[j][d4] = vreg[t];
    }
    __syncthreads();

    float c0 = 0.f, c1 = 0.f;
#pragma unroll 4
    for (int j = 0; j < 128; j++) {
        float p = probs[w][j];
        c0 = fmaf(p, tile[j][lane], c0);
        c1 = fmaf(p, tile[j][lane + 32], c1);
    }
    size_t obase = ((size_t)(b * SS + i)) * HID + h * DH;
    ctx[obase + lane] = c0;
    ctx[obase + lane + 32] = c1;
}

// =============================================================================
// LayerNorm over split-K partials: x = p0 + p1 + bias + res, then LN.
// =============================================================================
__global__ __launch_bounds__(256)
void ln_kernel(const float* __restrict__ Cp, const float* __restrict__ bias,
               const float* __restrict__ res, const float* __restrict__ g,
               const float* __restrict__ beta, float* __restrict__ out)
{
    int row = blockIdx.x;
    int t = threadIdx.x;
    int lane = t & 31, w = t >> 5;
    __shared__ float red[8];

    size_t idx = (size_t)row * HID + t;
    float x = Cp[idx] + Cp[(size_t)MM * HID + idx] + bias[t] + res[idx];

    float v = x;
#pragma unroll
    for (int o = 16; o; o >>= 1) v += __shfl_xor_sync(0xffffffffu, v, o);
    if (lane == 0) red[w] = v;
    __syncthreads();
    float mean;
    {
        float r = (lane < 8) ? red[lane] : 0.f;
#pragma unroll
        for (int o = 4; o; o >>= 1) r += __shfl_xor_sync(0xffffffffu, r, o);
        mean = __shfl_sync(0xffffffffu, r, 0) * (1.0f / HID);
    }
    float d = x - mean;
    v = d * d;
#pragma unroll
    for (int o = 16; o; o >>= 1) v += __shfl_xor_sync(0xffffffffu, v, o);
    __syncthreads();
    if (lane == 0) red[w] = v;
    __syncthreads();
    float var;
    {
        float r = (lane < 8) ? red[lane] : 0.f;
#pragma unroll
        for (int o = 4; o; o >>= 1) r += __shfl_xor_sync(0xffffffffu, r, o);
        var = __shfl_sync(0xffffffffu, r, 0) * (1.0f / HID);
    }
    float invs = rsqrtf(var + 1e-12f);
    out[idx] = d * invs * g[t] + beta[t];
}

// ---------------- launch -----------------------------------------------------
extern "C" void kernel_launch(void* const* d_in, const int* in_sizes, int n_in,
                              void* d_out, int out_size)
{
    const float* x       = (const float*)d_in[0];
    const float* mask    = (const float*)d_in[1];
    const float* Wq      = (const float*)d_in[2];
    const float* bq      = (const float*)d_in[3];
    const float* Wk      = (const float*)d_in[4];
    const float* bk      = (const float*)d_in[5];
    const float* Wv      = (const float*)d_in[6];
    const float* bv      = (const float*)d_in[7];
    const float* order_w = (const float*)d_in[8];
    const float* order_b = (const float*)d_in[9];
    const float* dist_w  = (const float*)d_in[10];
    const float* dist_b  = (const float*)d_in[11];
    const float* scalar  = (const float*)d_in[12];
    const float* AWq     = (const float*)d_in[13];
    const float* Abq     = (const float*)d_in[14];
    const float* AWk     = (const float*)d_in[15];
    const float* Abk     = (const float*)d_in[16];
    const float* Wd      = (const float*)d_in[17];
    const float* bd      = (const float*)d_in[18];
    const float* g1      = (const float*)d_in[19];
    const float* beta1   = (const float*)d_in[20];
    const float* W1      = (const float*)d_in[21];
    const float* b1      = (const float*)d_in[22];
    const float* W2      = (const float*)d_in[23];
    const float* b2      = (const float*)d_in[24];
    const float* g2      = (const float*)d_in[25];
    const float* beta2   = (const float*)d_in[26];
    float* out = (float*)d_out;

    float *P, *ctx, *hbuf, *part, *ffb, *wf, *bf;
    cudaGetSymbolAddress((void**)&P,    g_proj);
    cudaGetSymbolAddress((void**)&ctx,  g_ctx);
    cudaGetSymbolAddress((void**)&hbuf, g_h);
    cudaGetSymbolAddress((void**)&part, g_part);
    cudaGetSymbolAddress((void**)&ffb,  g_ff);
    cudaGetSymbolAddress((void**)&wf,   g_wf);
    cudaGetSymbolAddress((void**)&bf,   g_bf);

    // fused attack weights/biases
    fusew_kernel<<<dim3(8, 5), 256>>>(Wq, bq, Wk, bk, AWq, Abq, AWk, Abk, wf, bf);

    // all 5 projections in one kernel (320 blocks)
    proj_kernel<<<dim3(20, 16), 256>>>(x, Wq, bq, Wk, bk, Wv, bv, wf, bf, P);

    // fused attention (512 blocks)
    attn_kernel<<<dim3(SS / 8, NH, BB), 256>>>(P, mask, order_w, order_b,
                                               dist_w, dist_b, scalar, ctx);

    // output projection split-K=2 (256 blocks) + fused bias/res LN1
    gemm_partial<2><<<dim3(4, 32, 2), 256>>>(ctx, Wd, part, HID, HID);
    ln_kernel<<<MM, 256>>>(part, bd, x, g1, beta1, hbuf);

    // FFN
    gemm_g<4><<<dim3(16, 16), 256>>>(hbuf, W1, b1, ffb, FF, HID, 1);
    gemm_partial<2><<<dim3(4, 32, 2), 256>>>(ffb, W2, part, HID, FF);
    ln_kernel<<<MM, 256>>>(part, b2, hbuf, g2, beta2, out);
}

// round 4
// speedup vs baseline: 4.4340x; 1.0942x over previous
#include <cuda_runtime.h>
#include <math.h>

#define BB   8
#define SS   128
#define HID  256
#define NH   4
#define DH   64
#define FF   1024
#define MM   (BB*SS)        // 1024 rows
#define PSTR 1280           // proj buffer row stride: q|k|v|aq|ak

// ---------------- scratch ----------------------------------------------------
__device__ float g_proj[MM * PSTR];
__device__ float g_ctx [MM * HID];
__device__ float g_h   [MM * HID];
__device__ float g_part[4 * MM * HID]; // split-K=4 partials
__device__ float g_ff  [MM * FF];
__device__ float g_wf  [HID * 512];
__device__ float g_bf  [512];

// =============================================================================
// GEMM body: 128 threads, BM=64, BN=64, BK=16, per-thread 8x4.
// A tile stored k-major (transposed) so inner loop = 3x LDS.128 + 32x FFMA.
// Register-prefetch of next global K-tile.
// =============================================================================
__device__ __forceinline__ void gemm_body128(const float* __restrict__ A, int lda,
                                             const float* __restrict__ B, int ldb,
                                             int row0, int bcol0, int K,
                                             float acc[8][4])
{
    __shared__ float As[16][68];   // [k][m], pad 68 (16B-aligned rows, 2-way wr conflict max)
    __shared__ float Bs[16][64];   // [k][n]

    const int tid = threadIdx.x;       // 128
    const int tx = tid & 15;           // col group (4 cols)
    const int ty = tid >> 4;           // row group (8 rows)

    const int ar0 = tid >> 2;          // 0..31
    const int ar1 = ar0 + 32;
    const int ac  = (tid & 3) << 2;    // 0,4,8,12
    const int br0 = tid >> 4;          // 0..7
    const int br1 = br0 + 8;
    const int bc  = (tid & 15) << 2;

    const float* Ap0 = A + (size_t)(row0 + ar0) * lda + ac;
    const float* Ap1 = A + (size_t)(row0 + ar1) * lda + ac;
    const float* Bp0 = B + (size_t)br0 * ldb + bcol0 + bc;
    const float* Bp1 = B + (size_t)br1 * ldb + bcol0 + bc;

    float4 aR0 = *(const float4*)Ap0;
    float4 aR1 = *(const float4*)Ap1;
    float4 bR0 = *(const float4*)Bp0;
    float4 bR1 = *(const float4*)Bp1;

#pragma unroll
    for (int i = 0; i < 8; i++)
#pragma unroll
        for (int j = 0; j < 4; j++) acc[i][j] = 0.f;

    for (int k0 = 0; k0 < K; k0 += 16) {
        __syncthreads();
        As[ac + 0][ar0] = aR0.x; As[ac + 1][ar0] = aR0.y;
        As[ac + 2][ar0] = aR0.z; As[ac + 3][ar0] = aR0.w;
        As[ac + 0][ar1] = aR1.x; As[ac + 1][ar1] = aR1.y;
        As[ac + 2][ar1] = aR1.z; As[ac + 3][ar1] = aR1.w;
        *(float4*)&Bs[br0][bc] = bR0;
        *(float4*)&Bs[br1][bc] = bR1;
        __syncthreads();

        if (k0 + 16 < K) {
            aR0 = *(const float4*)(Ap0 + k0 + 16);
            aR1 = *(const float4*)(Ap1 + k0 + 16);
            bR0 = *(const float4*)(Bp0 + (size_t)(k0 + 16) * ldb);
            bR1 = *(const float4*)(Bp1 + (size_t)(k0 + 16) * ldb);
        }

#pragma unroll
        for (int kk = 0; kk < 16; kk++) {
            float4 a0 = *(const float4*)&As[kk][ty * 8];
            float4 a1 = *(const float4*)&As[kk][ty * 8 + 4];
            float4 b  = *(const float4*)&Bs[kk][tx << 2];
            float am[8] = {a0.x, a0.y, a0.z, a0.w, a1.x, a1.y, a1.z, a1.w};
#pragma unroll
            for (int i = 0; i < 8; i++) {
                acc[i][0] = fmaf(am[i], b.x, acc[i][0]);
                acc[i][1] = fmaf(am[i], b.y, acc[i][1]);
                acc[i][2] = fmaf(am[i], b.z, acc[i][2]);
                acc[i][3] = fmaf(am[i], b.w, acc[i][3]);
            }
        }
    }
}

// =============================================================================
// fusew: Wf[:,0:256]=Wq@AWq, Wf[:,256:512]=Wk@AWk, fused biases.
// grid (8,5), 128 threads.
// =============================================================================
__global__ __launch_bounds__(128)
void fusew_kernel(const float* __restrict__ Wq, const float* __restrict__ bq,
                  const float* __restrict__ Wk, const float* __restrict__ bk,
                  const float* __restrict__ AWq, const float* __restrict__ Abq,
                  const float* __restrict__ AWk, const float* __restrict__ Abk,
                  float* __restrict__ Wf, float* __restrict__ bf)
{
    const int seg = blockIdx.x >> 2;
    const int wcol0 = (blockIdx.x & 3) * 64;

    if (blockIdx.y == 4) {
        const float* bin = seg ? bk : bq;
        const float* AW  = seg ? AWk : AWq;
        const float* Ab  = seg ? Abk : Abq;
        __shared__ float red[128];
        int t = threadIdx.x;
        int c = t & 63, half = t >> 6;
        float s = 0.f;
        for (int d = half * 128; d < half * 128 + 128; d++)
            s += bin[d] * AW[(size_t)d * HID + wcol0 + c];
        red[t] = s;
        __syncthreads();
        if (half == 0)
            bf[seg * 256 + wcol0 + c] = red[c] + red[64 + c] + Ab[wcol0 + c];
        return;
    }

    const float* A = seg ? Wk : Wq;
    const float* B = seg ? AWk : AWq;
    const int row0 = blockIdx.y * 64;
    float acc[8][4];
    gemm_body128(A, HID, B, HID, row0, wcol0, HID, acc);

    const int tx = threadIdx.x & 15, ty = threadIdx.x >> 4;
#pragma unroll
    for (int i = 0; i < 8; i++) {
        int r = row0 + ty * 8 + i;
#pragma unroll
        for (int j = 0; j < 4; j++)
            Wf[(size_t)r * 512 + seg * 256 + wcol0 + (tx << 2) + j] = acc[i][j];
    }
}

// =============================================================================
// proj: all 5 projections. grid (20,16), 128 threads.
// =============================================================================
__global__ __launch_bounds__(128)
void proj_kernel(const float* __restrict__ x,
                 const float* __restrict__ Wq, const float* __restrict__ bq,
                 const float* __restrict__ Wk, const float* __restrict__ bk,
                 const float* __restrict__ Wv, const float* __restrict__ bv,
                 const float* __restrict__ Wf, const float* __restrict__ bf,
                 float* __restrict__ P)
{
    const int seg = blockIdx.x >> 2;
    const int wcol0 = (blockIdx.x & 3) * 64;
    const int row0 = blockIdx.y * 64;

    const float* W; const float* bias; int ldb; int bcol;
    if      (seg == 0) { W = Wq; bias = bq;        ldb = HID; bcol = wcol0; }
    else if (seg == 1) { W = Wk; bias = bk;        ldb = HID; bcol = wcol0; }
    else if (seg == 2) { W = Wv; bias = bv;        ldb = HID; bcol = wcol0; }
    else if (seg == 3) { W = Wf; bias = bf;        ldb = 512; bcol = wcol0; }
    else               { W = Wf; bias = bf + 256;  ldb = 512; bcol = 256 + wcol0; }

    float acc[8][4];
    gemm_body128(x, HID, W, ldb, row0, bcol, HID, acc);

    const int tx = threadIdx.x & 15, ty = threadIdx.x >> 4;
    const int ocol0 = blockIdx.x * 64;
#pragma unroll
    for (int i = 0; i < 8; i++) {
        int r = row0 + ty * 8 + i;
#pragma unroll
        for (int j = 0; j < 4; j++) {
            int c = (tx << 2) + j;
            P[(size_t)r * PSTR + ocol0 + c] = acc[i][j] + bias[wcol0 + c];
        }
    }
}

// =============================================================================
// Generic GEMM + bias (+gelu): W1. grid (N/64, M/64), 128 threads.
// =============================================================================
__global__ __launch_bounds__(128)
void gemm_g(const float* __restrict__ A, const float* __restrict__ B,
            const float* __restrict__ bias, float* __restrict__ C,
            int N, int K, int do_gelu)
{
    const int row0 = blockIdx.y * 64;
    const int col0 = blockIdx.x * 64;
    float acc[8][4];
    gemm_body128(A, K, B, N, row0, col0, K, acc);

    const int tx = threadIdx.x & 15, ty = threadIdx.x >> 4;
#pragma unroll
    for (int i = 0; i < 8; i++) {
        int r = row0 + ty * 8 + i;
#pragma unroll
        for (int j = 0; j < 4; j++) {
            int c = col0 + (tx << 2) + j;
            float v = acc[i][j] + bias[c];
            if (do_gelu) v = 0.5f * v * (1.0f + erff(v * 0.70710678118654752f));
            C[(size_t)r * N + c] = v;
        }
    }
}

// =============================================================================
// Split-K=4 partial GEMM (no bias). grid (N/64, M/64, 4).
// =============================================================================
__global__ __launch_bounds__(128)
void gemm_partial4(const float* __restrict__ A, const float* __restrict__ B,
                   float* __restrict__ Cp, int N, int K)
{
    const int ks = blockIdx.z;
    const int Ks = K >> 2;
    const int row0 = blockIdx.y * 64;
    const int col0 = blockIdx.x * 64;
    float acc[8][4];
    gemm_body128(A + (size_t)ks * Ks, K, B + (size_t)ks * Ks * N, N, row0, col0, Ks, acc);

    float* C = Cp + (size_t)ks * MM * HID;
    const int tx = threadIdx.x & 15, ty = threadIdx.x >> 4;
#pragma unroll
    for (int i = 0; i < 8; i++) {
        int r = row0 + ty * 8 + i;
#pragma unroll
        for (int j = 0; j < 4; j++) {
            int c = col0 + (tx << 2) + j;
            C[(size_t)r * N + c] = acc[i][j];
        }
    }
}

// =============================================================================
// Fused attention (unchanged): 256 threads, 8 warps = 8 queries of one (b,h).
// =============================================================================
__device__ __forceinline__ void softmax4(const float x[4], float p[4])
{
    float m = fmaxf(fmaxf(x[0], x[1]), fmaxf(x[2], x[3]));
#pragma unroll
    for (int o = 16; o; o >>= 1) m = fmaxf(m, __shfl_xor_sync(0xffffffffu, m, o));
    float e0 = __expf(x[0] - m), e1 = __expf(x[1] - m);
    float e2 = __expf(x[2] - m), e3 = __expf(x[3] - m);
    float s = e0 + e1 + e2 + e3;
#pragma unroll
    for (int o = 16; o; o >>= 1) s += __shfl_xor_sync(0xffffffffu, s, o);
    float r = 1.f / s;
    p[0] = e0 * r; p[1] = e1 * r; p[2] = e2 * r; p[3] = e3 * r;
}

__global__ __launch_bounds__(256)
void attn_kernel(const float* __restrict__ P, const float* __restrict__ mask,
                 const float* __restrict__ order_w, const float* __restrict__ order_b,
                 const float* __restrict__ dist_w, const float* __restrict__ dist_b,
                 const float* __restrict__ scalar, float* __restrict__ ctx)
{
    __shared__ float tile[128][68];
    __shared__ float qsh[8][64];
    __shared__ float probs[8][128];
    __shared__ float kokd[128][2];
    __shared__ float wsh[256];

    const int tid = threadIdx.x;
    const int lane = tid & 31;
    const int w = tid >> 5;
    const int h = blockIdx.y, b = blockIdx.z;
    const int i0 = blockIdx.x * 8;
    const int i = i0 + w;

    const size_t rowbase = ((size_t)b * SS) * PSTR + h * DH;

#pragma unroll
    for (int f = tid; f < 128 * 16; f += 256) {
        int j = f >> 4, d4 = (f & 15) << 2;
        *(float4*)&tile[j][d4] = *(const float4*)&P[rowbase + (size_t)j * PSTR + 256 + d4];
    }
#pragma unroll
    for (int f = tid; f < 8 * 16; f += 256) {
        int r = f >> 4, d4 = (f & 15) << 2;
        *(float4*)&qsh[r][d4] = *(const float4*)&P[rowbase + (size_t)(i0 + r) * PSTR + d4];
    }
    wsh[tid] = (tid < 128) ? order_w[tid] : dist_w[tid - 128];
    __syncthreads();

    float s[4] = {0, 0, 0, 0};
#pragma unroll
    for (int d4 = 0; d4 < 64; d4 += 4) {
        float4 qv = *(const float4*)&qsh[w][d4];
#pragma unroll
        for (int jj = 0; jj < 4; jj++) {
            float4 kv = *(const float4*)&tile[lane + 32 * jj][d4];
            s[jj] = fmaf(qv.x, kv.x, fmaf(qv.y, kv.y, fmaf(qv.z, kv.z, fmaf(qv.w, kv.w, s[jj]))));
        }
    }
    if (tid < 128) {
        float ko = 0, kd = 0;
#pragma unroll
        for (int d4 = 0; d4 < 64; d4 += 4) {
            float4 kv = *(const float4*)&tile[tid][d4];
            float4 ov = *(const float4*)&wsh[64 + d4];
            float4 dv = *(const float4*)&wsh[192 + d4];
            ko = fmaf(kv.x, ov.x, fmaf(kv.y, ov.y, fmaf(kv.z, ov.z, fmaf(kv.w, ov.w, ko))));
            kd = fmaf(kv.x, dv.x, fmaf(kv.y, dv.y, fmaf(kv.z, dv.z, fmaf(kv.w, dv.w, kd))));
        }
        kokd[tid][0] = ko; kokd[tid][1] = kd;
    }
    float qo = qsh[w][lane] * wsh[lane] + qsh[w][lane + 32] * wsh[32 + lane];
    float qd = qsh[w][lane] * wsh[128 + lane] + qsh[w][lane + 32] * wsh[160 + lane];
#pragma unroll
    for (int o = 16; o; o >>= 1) {
        qo += __shfl_xor_sync(0xffffffffu, qo, o);
        qd += __shfl_xor_sync(0xffffffffu, qd, o);
    }
    __syncthreads();

#pragma unroll
    for (int f = tid; f < 128 * 16; f += 256) {
        int j = f >> 4, d4 = (f & 15) << 2;
        *(float4*)&tile[j][d4] = *(const float4*)&P[rowbase + (size_t)j * PSTR + 1024 + d4];
    }
#pragma unroll
    for (int f = tid; f < 8 * 16; f += 256) {
        int r = f >> 4, d4 = (f & 15) << 2;
        *(float4*)&qsh[r][d4] = *(const float4*)&P[rowbase + (size_t)(i0 + r) * PSTR + 768 + d4];
    }
    __syncthreads();

    float as[4] = {0, 0, 0, 0};
#pragma unroll
    for (int d4 = 0; d4 < 64; d4 += 4) {
        float4 qv = *(const float4*)&qsh[w][d4];
#pragma unroll
        for (int jj = 0; jj < 4; jj++) {
            float4 kv = *(const float4*)&tile[lane + 32 * jj][d4];
            as[jj] = fmaf(qv.x, kv.x, fmaf(qv.y, kv.y, fmaf(qv.z, kv.z, fmaf(qv.w, kv.w, as[jj]))));
        }
    }
    __syncthreads();

    float4 vreg[8];
#pragma unroll
    for (int t = 0; t < 8; t++) {
        int f = tid + t * 256;
        int j = f >> 4, d4 = (f & 15) << 2;
        vreg[t] = *(const float4*)&P[rowbase + (size_t)j * PSTR + 512 + d4];
    }

    const float ob = order_b[0], db = dist_b[0], sc = scalar[0];
    const float inv = 0.125f;
    float rich[4], orig[4], att[4];
#pragma unroll
    for (int jj = 0; jj < 4; jj++) {
        int j = lane + 32 * jj;
        float pr_o = 1.f / (1.f + __expf(-(qo + kokd[j][0] + ob)));
        float gd = (j > i) ? 1.f : 0.f;
        float err_o = __logf(pr_o + 1e-24f) * gd + __logf(1.f - pr_o + 1e-24f) * (1.f - gd);
        float gdd = __logf(fabsf((float)(j - i)) + 1.f);
        float diff = gdd - (qd + kokd[j][1] + db);
        float err_d = -0.5f * diff * diff * sc * sc;
        float mk = mask[((size_t)b * SS + i) * SS + j];
        rich[jj] = (s[jj] + err_o + err_d) * inv + mk;
        orig[jj] = s[jj] * inv + mk;
        att[jj]  = as[jj] * inv + mk;
    }
    float rich_p[4], orig_p[4], att_p[4], comb[4], comb_p[4], fin[4], fin_p[4];
    softmax4(rich, rich_p);
    softmax4(orig, orig_p);
    softmax4(att, att_p);
#pragma unroll
    for (int jj = 0; jj < 4; jj++) comb[jj] = orig_p[jj] + 0.5f * rich_p[jj];
    softmax4(comb, comb_p);
#pragma unroll
    for (int jj = 0; jj < 4; jj++) fin[jj] = comb_p[jj] + 0.5f * att_p[jj];
    softmax4(fin, fin_p);
#pragma unroll
    for (int jj = 0; jj < 4; jj++) probs[w][lane + 32 * jj] = fin_p[jj];

#pragma unroll
    for (int t = 0; t < 8; t++) {
        int f = tid + t * 256;
        int j = f >> 4, d4 = (f & 15) << 2;
        *(float4*)&tile[j][d4] = vreg[t];
    }
    __syncthreads();

    float c0 = 0.f, c1 = 0.f;
#pragma unroll 4
    for (int j = 0; j < 128; j++) {
        float p = probs[w][j];
        c0 = fmaf(p, tile[j][lane], c0);
        c1 = fmaf(p, tile[j][lane + 32], c1);
    }
    size_t obase = ((size_t)(b * SS + i)) * HID + h * DH;
    ctx[obase + lane] = c0;
    ctx[obase + lane + 32] = c1;
}

// =============================================================================
// LayerNorm over 4 split-K partials + bias + residual.
// =============================================================================
__global__ __launch_bounds__(256)
void ln_kernel(const float* __restrict__ Cp, const float* __restrict__ bias,
               const float* __restrict__ res, const float* __restrict__ g,
               const float* __restrict__ beta, float* __restrict__ out)
{
    int row = blockIdx.x;
    int t = threadIdx.x;
    int lane = t & 31, w = t >> 5;
    __shared__ float red[8];

    const size_t SZ = (size_t)MM * HID;
    size_t idx = (size_t)row * HID + t;
    float x = Cp[idx] + Cp[SZ + idx] + Cp[2 * SZ + idx] + Cp[3 * SZ + idx]
            + bias[t] + res[idx];

    float v = x;
#pragma unroll
    for (int o = 16; o; o >>= 1) v += __shfl_xor_sync(0xffffffffu, v, o);
    if (lane == 0) red[w] = v;
    __syncthreads();
    float mean;
    {
        float r = (lane < 8) ? red[lane] : 0.f;
#pragma unroll
        for (int o = 4; o; o >>= 1) r += __shfl_xor_sync(0xffffffffu, r, o);
        mean = __shfl_sync(0xffffffffu, r, 0) * (1.0f / HID);
    }
    float d = x - mean;
    v = d * d;
#pragma unroll
    for (int o = 16; o; o >>= 1) v += __shfl_xor_sync(0xffffffffu, v, o);
    __syncthreads();
    if (lane == 0) red[w] = v;
    __syncthreads();
    float var;
    {
        float r = (lane < 8) ? red[lane] : 0.f;
#pragma unroll
        for (int o = 4; o; o >>= 1) r += __shfl_xor_sync(0xffffffffu, r, o);
        var = __shfl_sync(0xffffffffu, r, 0) * (1.0f / HID);
    }
    float invs = rsqrtf(var + 1e-12f);
    out[idx] = d * invs * g[t] + beta[t];
}

// ---------------- launch -----------------------------------------------------
extern "C" void kernel_launch(void* const* d_in, const int* in_sizes, int n_in,
                              void* d_out, int out_size)
{
    const float* x       = (const float*)d_in[0];
    const float* mask    = (const float*)d_in[1];
    const float* Wq      = (const float*)d_in[2];
    const float* bq      = (const float*)d_in[3];
    const float* Wk      = (const float*)d_in[4];
    const float* bk      = (const float*)d_in[5];
    const float* Wv      = (const float*)d_in[6];
    const float* bv      = (const float*)d_in[7];
    const float* order_w = (const float*)d_in[8];
    const float* order_b = (const float*)d_in[9];
    const float* dist_w  = (const float*)d_in[10];
    const float* dist_b  = (const float*)d_in[11];
    const float* scalar  = (const float*)d_in[12];
    const float* AWq     = (const float*)d_in[13];
    const float* Abq     = (const float*)d_in[14];
    const float* AWk     = (const float*)d_in[15];
    const float* Abk     = (const float*)d_in[16];
    const float* Wd      = (const float*)d_in[17];
    const float* bd      = (const float*)d_in[18];
    const float* g1      = (const float*)d_in[19];
    const float* beta1   = (const float*)d_in[20];
    const float* W1      = (const float*)d_in[21];
    const float* b1      = (const float*)d_in[22];
    const float* W2      = (const float*)d_in[23];
    const float* b2      = (const float*)d_in[24];
    const float* g2      = (const float*)d_in[25];
    const float* beta2   = (const float*)d_in[26];
    float* out = (float*)d_out;

    float *P, *ctx, *hbuf, *part, *ffb, *wf, *bf;
    cudaGetSymbolAddress((void**)&P,    g_proj);
    cudaGetSymbolAddress((void**)&ctx,  g_ctx);
    cudaGetSymbolAddress((void**)&hbuf, g_h);
    cudaGetSymbolAddress((void**)&part, g_part);
    cudaGetSymbolAddress((void**)&ffb,  g_ff);
    cudaGetSymbolAddress((void**)&wf,   g_wf);
    cudaGetSymbolAddress((void**)&bf,   g_bf);

    // fused attack weights/biases
    fusew_kernel<<<dim3(8, 5), 128>>>(Wq, bq, Wk, bk, AWq, Abq, AWk, Abk, wf, bf);

    // all 5 projections (320 blocks)
    proj_kernel<<<dim3(20, 16), 128>>>(x, Wq, bq, Wk, bk, Wv, bv, wf, bf, P);

    // fused attention (512 blocks)
    attn_kernel<<<dim3(SS / 8, NH, BB), 256>>>(P, mask, order_w, order_b,
                                               dist_w, dist_b, scalar, ctx);

    // output projection split-K=4 (256 blocks) + fused bias/res LN1
    gemm_partial4<<<dim3(4, 16, 4), 128>>>(ctx, Wd, part, HID, HID);
    ln_kernel<<<MM, 256>>>(part, bd, x, g1, beta1, hbuf);

    // FFN
    gemm_g<<<dim3(16, 16), 128>>>(hbuf, W1, b1, ffb, FF, HID, 1);
    gemm_partial4<<<dim3(4, 16, 4), 128>>>(ffb, W2, part, HID, FF);
    ln_kernel<<<MM, 256>>>(part, b2, hbuf, g2, beta2, out);
}